// round 3
// baseline (speedup 1.0000x reference)
#include <cuda_runtime.h>
#include <math.h>

// Problem constants
#define BDIM 4
#define TDIM 4096
#define CDIM 1024
#define HDIM 2048
#define MTOT (BDIM * TDIM)   // 16384

// Scratch (device globals: allocation-free per harness rules)
__device__ float g_s[(size_t)MTOT * HDIM];       // s, later s*agg   (128 MB)
__device__ float g_h[(size_t)MTOT * 2 * HDIM];   // h = x@W_agg*sqk  (256 MB)

// ---------------------------------------------------------------------------
// Tiled fp32 GEMM: C[M,N] = A[M,K] @ W[K,N], row-major everywhere.
// 128x128 block tile, BK=16, 256 threads, 8x8 per thread, smem double buffer.
// EPI: 0 = y*scale[n] ; 1 = silu(y*scale[n]) ; 2 = plain
// ---------------------------------------------------------------------------
constexpr int BM = 128, BN = 128, BK = 16;
constexpr int APAD = 4;  // pad transposed A-tile rows to soften store conflicts

template <int EPI>
__global__ __launch_bounds__(256)
void sgemm(const float* __restrict__ A, const float* __restrict__ W,
           float* __restrict__ Cout, const float* __restrict__ scale,
           int M, int N, int K)
{
    __shared__ float As[2][BK][BM + APAD];
    __shared__ float Bs[2][BK][BN];

    const int tid = threadIdx.x;
    const int bn = blockIdx.x * BN;
    const int bm = blockIdx.y * BM;
    const int tx = tid & 15;        // 0..15  -> n sub-tile
    const int ty = tid >> 4;        // 0..15  -> m sub-tile

    // Global load mapping: 512 float4 for A-tile (128x16), 512 for B-tile (16x128)
    const int arow0 = tid >> 2;          // 0..63 (second load +64)
    const int acol  = (tid & 3) * 4;     // 0,4,8,12
    const int brow0 = tid >> 5;          // 0..7  (second load +8)
    const int bcol  = (tid & 31) * 4;    // 0..124

    const float* Aptr = A + (size_t)bm * K;
    const float* Wptr = W + bn;

    float4 aReg[2], bReg[2];

    // Prologue: load k-tile 0
#pragma unroll
    for (int i = 0; i < 2; i++) {
        int ar = arow0 + i * 64;
        aReg[i] = *(const float4*)(Aptr + (size_t)ar * K + acol);
        int br = brow0 + i * 8;
        bReg[i] = *(const float4*)(Wptr + (size_t)br * N + bcol);
    }
#pragma unroll
    for (int i = 0; i < 2; i++) {
        int ar = arow0 + i * 64;
        As[0][acol + 0][ar] = aReg[i].x;
        As[0][acol + 1][ar] = aReg[i].y;
        As[0][acol + 2][ar] = aReg[i].z;
        As[0][acol + 3][ar] = aReg[i].w;
        int br = brow0 + i * 8;
        *(float4*)(&Bs[0][br][bcol]) = bReg[i];
    }
    __syncthreads();

    float acc[8][8] = {};

    const int ntiles = K / BK;
    for (int t = 0; t < ntiles; ++t) {
        const int buf = t & 1;
        // Prefetch next k-tile from global into registers
        if (t + 1 < ntiles) {
            const int k0 = (t + 1) * BK;
#pragma unroll
            for (int i = 0; i < 2; i++) {
                int ar = arow0 + i * 64;
                aReg[i] = *(const float4*)(Aptr + (size_t)ar * K + k0 + acol);
                int br = brow0 + i * 8;
                bReg[i] = *(const float4*)(Wptr + (size_t)(k0 + br) * N + bcol);
            }
        }
        // Compute on current buffer
#pragma unroll
        for (int kk = 0; kk < BK; ++kk) {
            float4 a0 = *(const float4*)(&As[buf][kk][ty * 8]);
            float4 a1 = *(const float4*)(&As[buf][kk][ty * 8 + 4]);
            float4 b0 = *(const float4*)(&Bs[buf][kk][tx * 8]);
            float4 b1 = *(const float4*)(&Bs[buf][kk][tx * 8 + 4]);
            float av[8] = {a0.x, a0.y, a0.z, a0.w, a1.x, a1.y, a1.z, a1.w};
            float bv[8] = {b0.x, b0.y, b0.z, b0.w, b1.x, b1.y, b1.z, b1.w};
#pragma unroll
            for (int i = 0; i < 8; i++)
#pragma unroll
                for (int j = 0; j < 8; j++)
                    acc[i][j] = fmaf(av[i], bv[j], acc[i][j]);
        }
        // Stage next tile into the other buffer
        if (t + 1 < ntiles) {
            const int nb = buf ^ 1;
#pragma unroll
            for (int i = 0; i < 2; i++) {
                int ar = arow0 + i * 64;
                As[nb][acol + 0][ar] = aReg[i].x;
                As[nb][acol + 1][ar] = aReg[i].y;
                As[nb][acol + 2][ar] = aReg[i].z;
                As[nb][acol + 3][ar] = aReg[i].w;
                int br = brow0 + i * 8;
                *(float4*)(&Bs[nb][br][bcol]) = bReg[i];
            }
            __syncthreads();
        }
    }

    // Epilogue
    float sc[8];
    if (EPI == 0 || EPI == 1) {
#pragma unroll
        for (int j = 0; j < 8; j++) sc[j] = scale[bn + tx * 8 + j];
    }
#pragma unroll
    for (int i = 0; i < 8; i++) {
        int m = bm + ty * 8 + i;
        float* crow = Cout + (size_t)m * N + bn + tx * 8;
#pragma unroll
        for (int j = 0; j < 8; j += 4) {
            float vv[4];
#pragma unroll
            for (int q = 0; q < 4; q++) {
                float y = acc[i][j + q];
                if (EPI == 0 || EPI == 1) y *= sc[j + q];
                if (EPI == 1) y = y / (1.0f + expf(-y));  // silu
                vv[q] = y;
            }
            *(float4*)(crow + j) = make_float4(vv[0], vv[1], vv[2], vv[3]);
        }
    }
}

// ---------------------------------------------------------------------------
// Fused polynomial + causal running mean + gate:
//   poly[t] = c0 + c0*c1,  acc = cumsum_t(poly),  s[t] *= acc/(t+1)
// One thread per (batch, channel); loads coalesced across channels.
// ---------------------------------------------------------------------------
__global__ void cumsum_fuse(const float* __restrict__ h, float* __restrict__ s)
{
    const int ch = blockIdx.x * blockDim.x + threadIdx.x;  // 0..HDIM-1
    const int b  = blockIdx.y;
    const float* hp = h + (size_t)b * TDIM * (2 * HDIM) + ch;
    float* sp = s + (size_t)b * TDIM * HDIM + ch;

    float acc = 0.0f;
#pragma unroll 4
    for (int t = 0; t < TDIM; ++t) {
        float c0 = hp[(size_t)t * (2 * HDIM)];
        float c1 = hp[(size_t)t * (2 * HDIM) + HDIM];
        acc += fmaf(c0, c1, c0);            // acc += c0 + c0*c1
        float val = acc / (float)(t + 1);   // causal running mean
        size_t off = (size_t)t * HDIM;
        sp[off] = sp[off] * val;            // gate: s * agg (in place)
    }
}

// ---------------------------------------------------------------------------
// Launch
// ---------------------------------------------------------------------------
extern "C" void kernel_launch(void* const* d_in, const int* in_sizes, int n_in,
                              void* d_out, int out_size)
{
    const float* x     = (const float*)d_in[0];
    const float* W_sel = (const float*)d_in[1];
    const float* W_agg = (const float*)d_in[2];
    const float* W_out = (const float*)d_in[3];
    const float* sqk_q = (const float*)d_in[4];
    const float* sqk_k = (const float*)d_in[5];
    float* out = (float*)d_out;

    float *s_ptr, *h_ptr;
    cudaGetSymbolAddress((void**)&s_ptr, g_s);
    cudaGetSymbolAddress((void**)&h_ptr, g_h);

    dim3 blk(256);
    // s = silu((x @ W_sel) * sqk_q)            [16384 x 2048, K=1024]
    sgemm<1><<<dim3(HDIM / BN, MTOT / BM), blk>>>(x, W_sel, s_ptr, sqk_q,
                                                  MTOT, HDIM, CDIM);
    // h = (x @ W_agg) * sqk_k                  [16384 x 4096, K=1024]
    sgemm<0><<<dim3(2 * HDIM / BN, MTOT / BM), blk>>>(x, W_agg, h_ptr, sqk_k,
                                                      MTOT, 2 * HDIM, CDIM);
    // poly -> causal running mean -> s *= agg  (in place on g_s)
    cumsum_fuse<<<dim3(HDIM / 64, BDIM), 64>>>(h_ptr, s_ptr);
    // out = (s*agg) @ W_out                    [16384 x 1024, K=2048]
    sgemm<2><<<dim3(CDIM / BN, MTOT / BM), blk>>>(s_ptr, W_out, out, nullptr,
                                                  MTOT, CDIM, HDIM);
}

// round 4
// speedup vs baseline: 2.1520x; 2.1520x over previous
#include <cuda_runtime.h>
#include <cstdint>
#include <math.h>

// Problem constants
#define BDIM 4
#define TDIM 4096
#define CDIM 1024
#define HDIM 2048
#define MTOT (BDIM * TDIM)   // 16384

// Scratch (device globals: allocation-free per harness rules)
__device__ float g_s[(size_t)MTOT * HDIM];        // s, later s*agg (tf32-rounded)
__device__ float g_h[(size_t)MTOT * 2 * HDIM];    // h
__device__ float g_xr[(size_t)MTOT * CDIM];       // x rounded to tf32
__device__ float g_ws[(size_t)CDIM * HDIM];       // W_sel rounded
__device__ float g_wa[(size_t)CDIM * 2 * HDIM];   // W_agg rounded
__device__ float g_wo[(size_t)HDIM * CDIM];       // W_out rounded

// ---------------------------------------------------------------------------
// Tensor-core tf32 GEMM: C[M,N] = A[M,K] @ W[K,N], row-major.
// 128x128x32 block tile, 256 threads (8 warps 2x4, warp tile 64x32),
// 3-stage cp.async pipeline, ldmatrix A frags, LDS B frags.
// EPI: 0 = y*scale[n] ; 1 = silu(y*scale[n]) ; 2 = plain
// ---------------------------------------------------------------------------
constexpr int BM = 128, BN = 128, BK = 32;
constexpr int ASTR = BK + 4;          // 36 floats per A row (LDSM conflict-free)
constexpr int BSTR = BN + 8;          // 136 floats per B row (LDS conflict-free)
constexpr int ASZ = BM * ASTR;        // 4608 floats per stage
constexpr int BSZ = BK * BSTR;        // 4352 floats per stage
constexpr int STAGES = 3;
constexpr int SMEM_BYTES = STAGES * (ASZ + BSZ) * 4;  // 107520

__device__ __forceinline__ void ldsm4(uint32_t* r, uint32_t saddr) {
    asm volatile("ldmatrix.sync.aligned.m8n8.x4.shared.b16 {%0,%1,%2,%3}, [%4];"
                 : "=r"(r[0]), "=r"(r[1]), "=r"(r[2]), "=r"(r[3]) : "r"(saddr));
}
__device__ __forceinline__ void mma_tf32(float4& c, const uint32_t* a,
                                         uint32_t b0, uint32_t b1) {
    asm volatile(
        "mma.sync.aligned.m16n8k8.row.col.f32.tf32.tf32.f32 "
        "{%0,%1,%2,%3}, {%4,%5,%6,%7}, {%8,%9}, {%0,%1,%2,%3};"
        : "+f"(c.x), "+f"(c.y), "+f"(c.z), "+f"(c.w)
        : "r"(a[0]), "r"(a[1]), "r"(a[2]), "r"(a[3]), "r"(b0), "r"(b1));
}
__device__ __forceinline__ void cpasync16(uint32_t saddr, const void* g) {
    asm volatile("cp.async.cg.shared.global [%0], [%1], 16;" :: "r"(saddr), "l"(g));
}
__device__ __forceinline__ float tf32r(float v) {
    uint32_t u;
    asm("cvt.rna.tf32.f32 %0, %1;" : "=r"(u) : "f"(v));
    return __uint_as_float(u);
}

template <int EPI>
__global__ __launch_bounds__(256, 2)
void tgemm(const float* __restrict__ A, const float* __restrict__ W,
           float* __restrict__ C, const float* __restrict__ scale,
           int M, int N, int K)
{
    extern __shared__ float sm[];
    float* Asm = sm;
    float* Bsm = sm + STAGES * ASZ;
    const uint32_t sA = (uint32_t)__cvta_generic_to_shared(Asm);
    const uint32_t sB = (uint32_t)__cvta_generic_to_shared(Bsm);

    const int tid  = threadIdx.x;
    const int lane = tid & 31;
    const int wid  = tid >> 5;
    const int wm   = (wid >> 2) * 64;   // warp m offset in tile
    const int wn   = (wid & 3) * 32;    // warp n offset in tile
    const int bm   = blockIdx.y * BM;
    const int bn   = blockIdx.x * BN;

    const int ntiles = K >> 5;

    // ldmatrix per-lane word offset (A): tiles ordered a0,a1,a2,a3
    const int tile = lane >> 3, rin = lane & 7;
    const int a_lane = (wm + (tile & 1) * 8 + rin) * ASTR + (tile >> 1) * 4;
    // B per-lane word offset
    const int b_lane = (lane & 3) * BSTR + wn + (lane >> 2);

    auto issue_tile = [&](int t, int buf) {
        const int k0 = t << 5;
#pragma unroll
        for (int i = 0; i < 4; ++i) {
            int idx = tid + (i << 8);
            int ar = idx >> 3, ac = (idx & 7) << 2;
            cpasync16(sA + (uint32_t)(buf * ASZ + ar * ASTR + ac) * 4,
                      A + (size_t)(bm + ar) * K + k0 + ac);
            int br = idx >> 5, bc = (idx & 31) << 2;
            cpasync16(sB + (uint32_t)(buf * BSZ + br * BSTR + bc) * 4,
                      W + (size_t)(k0 + br) * N + bn + bc);
        }
    };

    // Prologue: fill the 3-stage ring
    issue_tile(0, 0);
    asm volatile("cp.async.commit_group;");
    issue_tile(1, 1);
    asm volatile("cp.async.commit_group;");
    issue_tile(2, 2);
    asm volatile("cp.async.commit_group;");
    asm volatile("cp.async.wait_group 2;");
    __syncthreads();

    float4 acc[4][4];
#pragma unroll
    for (int i = 0; i < 4; i++)
#pragma unroll
        for (int j = 0; j < 4; j++) acc[i][j] = make_float4(0.f, 0.f, 0.f, 0.f);

    int buf = 0;
    for (int t = 0; t < ntiles; ++t) {
        const int aoff = buf * ASZ, boff = buf * BSZ;
#pragma unroll
        for (int ks = 0; ks < 4; ++ks) {
            uint32_t af[4][4];
#pragma unroll
            for (int i = 0; i < 4; ++i)
                ldsm4(af[i], sA + (uint32_t)(aoff + a_lane + i * 16 * ASTR + ks * 8) * 4);
            uint32_t bf[4][2];
#pragma unroll
            for (int j = 0; j < 4; ++j) {
                bf[j][0] = __float_as_uint(Bsm[boff + b_lane + (ks * 8) * BSTR + j * 8]);
                bf[j][1] = __float_as_uint(Bsm[boff + b_lane + (ks * 8 + 4) * BSTR + j * 8]);
            }
#pragma unroll
            for (int i = 0; i < 4; ++i)
#pragma unroll
                for (int j = 0; j < 4; ++j)
                    mma_tf32(acc[i][j], af[i], bf[j][0], bf[j][1]);
        }
        __syncthreads();                       // everyone done reading buf
        if (t + STAGES < ntiles) issue_tile(t + STAGES, buf);
        asm volatile("cp.async.commit_group;");
        asm volatile("cp.async.wait_group 2;"); // next stage's data landed
        __syncthreads();
        buf = (buf == STAGES - 1) ? 0 : buf + 1;
    }

    // Epilogue
    const int qr = lane >> 2;             // 0..7
    const int qc = (lane & 3) << 1;       // 0,2,4,6
#pragma unroll
    for (int i = 0; i < 4; ++i) {
        const int m0 = bm + wm + i * 16 + qr;
#pragma unroll
        for (int j = 0; j < 4; ++j) {
            const int n0 = bn + wn + j * 8 + qc;
            float v0 = acc[i][j].x, v1 = acc[i][j].y;
            float v2 = acc[i][j].z, v3 = acc[i][j].w;
            if (EPI == 0 || EPI == 1) {
                float s0 = scale[n0], s1 = scale[n0 + 1];
                v0 *= s0; v1 *= s1; v2 *= s0; v3 *= s1;
            }
            if (EPI == 1) {
                v0 = v0 / (1.f + __expf(-v0));
                v1 = v1 / (1.f + __expf(-v1));
                v2 = v2 / (1.f + __expf(-v2));
                v3 = v3 / (1.f + __expf(-v3));
            }
            *(float2*)(C + (size_t)m0 * N + n0)       = make_float2(v0, v1);
            *(float2*)(C + (size_t)(m0 + 8) * N + n0) = make_float2(v2, v3);
        }
    }
}

// ---------------------------------------------------------------------------
// Pre-round fp32 -> tf32 (rna) so mma inputs carry no truncation bias.
// ---------------------------------------------------------------------------
__global__ void round_tf32(const float4* __restrict__ in, float4* __restrict__ out,
                           int n4)
{
    int i = blockIdx.x * blockDim.x + threadIdx.x;
    if (i < n4) {
        float4 v = in[i];
        v.x = tf32r(v.x); v.y = tf32r(v.y); v.z = tf32r(v.z); v.w = tf32r(v.w);
        out[i] = v;
    }
}

// ---------------------------------------------------------------------------
// Fused polynomial + causal running mean + gate (+ tf32 rounding for GEMM3):
//   poly[t] = c0 + c0*c1,  acc = cumsum_t(poly),  s[t] = tf32(s[t]*acc/(t+1))
// ---------------------------------------------------------------------------
__global__ void cumsum_fuse(const float* __restrict__ h, float* __restrict__ s)
{
    const int ch = blockIdx.x * blockDim.x + threadIdx.x;  // 0..HDIM-1
    const int b  = blockIdx.y;
    const float* hp = h + (size_t)b * TDIM * (2 * HDIM) + ch;
    float* sp = s + (size_t)b * TDIM * HDIM + ch;

    float acc = 0.0f;
#pragma unroll 4
    for (int t = 0; t < TDIM; ++t) {
        float c0 = hp[(size_t)t * (2 * HDIM)];
        float c1 = hp[(size_t)t * (2 * HDIM) + HDIM];
        acc += fmaf(c0, c1, c0);            // acc += c0 + c0*c1
        float val = acc / (float)(t + 1);   // causal running mean
        size_t off = (size_t)t * HDIM;
        sp[off] = tf32r(sp[off] * val);     // gate, rounded for next mma
    }
}

// ---------------------------------------------------------------------------
// Launch
// ---------------------------------------------------------------------------
extern "C" void kernel_launch(void* const* d_in, const int* in_sizes, int n_in,
                              void* d_out, int out_size)
{
    const float* x     = (const float*)d_in[0];
    const float* W_sel = (const float*)d_in[1];
    const float* W_agg = (const float*)d_in[2];
    const float* W_out = (const float*)d_in[3];
    const float* sqk_q = (const float*)d_in[4];
    const float* sqk_k = (const float*)d_in[5];
    float* out = (float*)d_out;

    float *s_p, *h_p, *xr, *ws, *wa, *wo;
    cudaGetSymbolAddress((void**)&s_p, g_s);
    cudaGetSymbolAddress((void**)&h_p, g_h);
    cudaGetSymbolAddress((void**)&xr, g_xr);
    cudaGetSymbolAddress((void**)&ws, g_ws);
    cudaGetSymbolAddress((void**)&wa, g_wa);
    cudaGetSymbolAddress((void**)&wo, g_wo);

    cudaFuncSetAttribute(tgemm<0>, cudaFuncAttributeMaxDynamicSharedMemorySize, SMEM_BYTES);
    cudaFuncSetAttribute(tgemm<1>, cudaFuncAttributeMaxDynamicSharedMemorySize, SMEM_BYTES);
    cudaFuncSetAttribute(tgemm<2>, cudaFuncAttributeMaxDynamicSharedMemorySize, SMEM_BYTES);

    // Pre-round all GEMM inputs to tf32 (rna, unbiased)
    {
        int n4;
        n4 = MTOT * CDIM / 4;
        round_tf32<<<(n4 + 255) / 256, 256>>>((const float4*)x, (float4*)xr, n4);
        n4 = CDIM * HDIM / 4;
        round_tf32<<<(n4 + 255) / 256, 256>>>((const float4*)W_sel, (float4*)ws, n4);
        n4 = CDIM * 2 * HDIM / 4;
        round_tf32<<<(n4 + 255) / 256, 256>>>((const float4*)W_agg, (float4*)wa, n4);
        n4 = HDIM * CDIM / 4;
        round_tf32<<<(n4 + 255) / 256, 256>>>((const float4*)W_out, (float4*)wo, n4);
    }

    dim3 blk(256);
    // s = silu((x @ W_sel) * sqk_q)            [16384 x 2048, K=1024]
    tgemm<1><<<dim3(HDIM / BN, MTOT / BM), blk, SMEM_BYTES>>>(
        xr, ws, s_p, sqk_q, MTOT, HDIM, CDIM);
    // h = (x @ W_agg) * sqk_k                  [16384 x 4096, K=1024]
    tgemm<0><<<dim3(2 * HDIM / BN, MTOT / BM), blk, SMEM_BYTES>>>(
        xr, wa, h_p, sqk_k, MTOT, 2 * HDIM, CDIM);
    // poly -> causal running mean -> s *= agg  (in place on g_s, tf32-rounded)
    cumsum_fuse<<<dim3(HDIM / 64, BDIM), 64>>>(h_p, s_p);
    // out = (s*agg) @ W_out                    [16384 x 1024, K=2048]
    tgemm<2><<<dim3(CDIM / BN, MTOT / BM), blk, SMEM_BYTES>>>(
        s_p, wo, out, nullptr, MTOT, CDIM, HDIM);
}

// round 10
// speedup vs baseline: 9.2698x; 4.3076x over previous
#include <cuda_runtime.h>
#include <cuda_fp16.h>
#include <cstdint>
#include <math.h>

// Problem constants
#define BDIM 4
#define TDIM 4096
#define CDIM 1024
#define HDIM 2048
#define MTOT (BDIM * TDIM)   // 16384
#define NCH  32              // cumsum chunks
#define CLEN (TDIM / NCH)    // 128

// Scratch (device globals: allocation-free per harness rules)
__device__ float  g_s [(size_t)MTOT * HDIM];        // silu branch (fp32)
__device__ float  g_h [(size_t)MTOT * 2 * HDIM];    // agg branch (fp32)
__device__ __half g_sh[(size_t)MTOT * HDIM];        // gated s*agg (fp16, GEMM3 A)
__device__ __half g_xh[(size_t)MTOT * CDIM];        // x fp16
__device__ __half g_wsh[(size_t)HDIM * CDIM];       // W_sel^T fp16 [N,K]
__device__ __half g_wah[(size_t)2 * HDIM * CDIM];   // W_agg^T fp16 [N,K]
__device__ __half g_woh[(size_t)CDIM * HDIM];       // W_out^T fp16 [N,K]
__device__ float  g_part[BDIM * NCH * HDIM];        // cumsum partials

// ---------------------------------------------------------------------------
// PTX helpers (all plain sm_80-era features: compile under compute_103)
// ---------------------------------------------------------------------------
__device__ __forceinline__ void cpasync16(uint32_t saddr, const void* g) {
    asm volatile("cp.async.cg.shared.global [%0], [%1], 16;" :: "r"(saddr), "l"(g));
}
__device__ __forceinline__ void ldsm4(uint32_t* r, uint32_t saddr) {
    asm volatile("ldmatrix.sync.aligned.m8n8.x4.shared.b16 {%0,%1,%2,%3}, [%4];"
                 : "=r"(r[0]), "=r"(r[1]), "=r"(r[2]), "=r"(r[3]) : "r"(saddr));
}
__device__ __forceinline__ void mma_f16(float* c, const uint32_t* a,
                                        uint32_t b0, uint32_t b1) {
    asm volatile(
        "mma.sync.aligned.m16n8k16.row.col.f32.f16.f16.f32 "
        "{%0,%1,%2,%3}, {%4,%5,%6,%7}, {%8,%9}, {%0,%1,%2,%3};"
        : "+f"(c[0]), "+f"(c[1]), "+f"(c[2]), "+f"(c[3])
        : "r"(a[0]), "r"(a[1]), "r"(a[2]), "r"(a[3]), "r"(b0), "r"(b1));
}

// ---------------------------------------------------------------------------
// fp16 tensor-core GEMM: C[M,N](fp32) = A[M,K](fp16) @ Wt[N,K](fp16)^T.
// 128x128 block tile, BK=64 halves (128B rows), 3-stage cp.async ring,
// 256 threads = 8 warps (2x4), warp tile 64x32.
// Padded rows: 72 halves (144B = 36 words) -> ldmatrix & B-LDS conflict-free.
// EPI: 0 = y*scale[n] ; 1 = silu(y*scale[n]) ; 2 = plain
// ---------------------------------------------------------------------------
constexpr int BM = 128, BN = 128, BKH = 64;
constexpr int KPAD = 72;                       // halves per padded row
constexpr int ROWB = KPAD * 2;                 // 144 bytes per row
constexpr int ATILE_B = BM * ROWB;             // 18432 bytes
constexpr int STAGE_B = 2 * ATILE_B;           // A + B per stage (36864)
constexpr int STAGES = 3;
constexpr int SMEM_BYTES = STAGES * STAGE_B;   // 110592

template <int EPI>
__global__ __launch_bounds__(256, 2)
void hgemm(const __half* __restrict__ A, const __half* __restrict__ Wt,
           float* __restrict__ C, const float* __restrict__ scale,
           int M, int N, int K)
{
    extern __shared__ __half sm[];
    const uint32_t smb = (uint32_t)__cvta_generic_to_shared(sm);

    const int tid  = threadIdx.x;
    const int lane = tid & 31;
    const int wid  = tid >> 5;
    const int wm   = (wid >> 2) * 64;     // warp m offset
    const int wn   = (wid & 3) * 32;      // warp n offset
    const int bm   = blockIdx.y * BM;
    const int bn   = blockIdx.x * BN;
    const int nt   = K / BKH;

    // ldmatrix.x4 lane offset (A): row = lane%16, kcol = (lane/16)*8 halves
    const uint32_t a_lane = (uint32_t)((lane & 15) * ROWB + (lane >> 4) * 16);
    // B scalar-LDS lane mapping: n = lane/4, k = (lane%4)*2
    const int bn_lane = lane >> 2;
    const int bk_lane = (lane & 3) * 2;

    auto issue_tile = [&](int t, int s) {
        const int k0 = t * BKH;
        const uint32_t ab = smb + (uint32_t)s * STAGE_B;
        const uint32_t bb = ab + ATILE_B;
#pragma unroll
        for (int i = 0; i < 4; ++i) {
            int idx = tid + (i << 8);            // 0..1023
            int r = idx >> 3, c = idx & 7;
            uint32_t dst = (uint32_t)(r * ROWB + c * 16);
            cpasync16(ab + dst, A  + (size_t)(bm + r) * K + k0 + c * 8);
            cpasync16(bb + dst, Wt + (size_t)(bn + r) * K + k0 + c * 8);
        }
    };

    // Prologue: fill ring
    issue_tile(0, 0);
    asm volatile("cp.async.commit_group;");
    issue_tile(1, 1);
    asm volatile("cp.async.commit_group;");
    issue_tile(2, 2);
    asm volatile("cp.async.commit_group;");
    asm volatile("cp.async.wait_group 2;");
    __syncthreads();

    float acc[4][4][4];
#pragma unroll
    for (int i = 0; i < 4; ++i)
#pragma unroll
        for (int j = 0; j < 4; ++j)
#pragma unroll
            for (int q = 0; q < 4; ++q) acc[i][j][q] = 0.f;

    int buf = 0;
    for (int t = 0; t < nt; ++t) {
        const uint32_t ab = smb + (uint32_t)buf * STAGE_B;
        const __half* Bgen = sm + (size_t)buf * (STAGE_B / 2) + (ATILE_B / 2);
#pragma unroll
        for (int ks = 0; ks < 4; ++ks) {         // 4 x k16
            uint32_t af[4][4];
#pragma unroll
            for (int i = 0; i < 4; ++i)
                ldsm4(af[i], ab + (uint32_t)((wm + i * 16) * ROWB + ks * 32) + a_lane);
            uint32_t bf[4][2];
#pragma unroll
            for (int j = 0; j < 4; ++j) {
                const __half* bp = Bgen + (size_t)(wn + j * 8 + bn_lane) * KPAD
                                        + ks * 16 + bk_lane;
                bf[j][0] = *(const uint32_t*)bp;
                bf[j][1] = *(const uint32_t*)(bp + 8);
            }
#pragma unroll
            for (int i = 0; i < 4; ++i)
#pragma unroll
                for (int j = 0; j < 4; ++j)
                    mma_f16(acc[i][j], af[i], bf[j][0], bf[j][1]);
        }
        __syncthreads();                         // done reading buf
        if (t + STAGES < nt) issue_tile(t + STAGES, buf);
        asm volatile("cp.async.commit_group;");
        asm volatile("cp.async.wait_group 2;");  // tile t+1 landed
        __syncthreads();
        buf = (buf == STAGES - 1) ? 0 : buf + 1;
    }

    // Epilogue: c-fragment direct stores (float2 per frag row)
    const int qr = lane >> 2;              // 0..7
    const int qc = (lane & 3) << 1;        // 0,2,4,6
#pragma unroll
    for (int i = 0; i < 4; ++i) {
        const int m0 = bm + wm + i * 16 + qr;
#pragma unroll
        for (int j = 0; j < 4; ++j) {
            const int n0 = bn + wn + j * 8 + qc;
            float v0 = acc[i][j][0], v1 = acc[i][j][1];
            float v2 = acc[i][j][2], v3 = acc[i][j][3];
            if (EPI == 0 || EPI == 1) {
                float s0 = scale[n0], s1 = scale[n0 + 1];
                v0 *= s0; v1 *= s1; v2 *= s0; v3 *= s1;
            }
            if (EPI == 1) {
                v0 = v0 / (1.f + __expf(-v0));
                v1 = v1 / (1.f + __expf(-v1));
                v2 = v2 / (1.f + __expf(-v2));
                v3 = v3 / (1.f + __expf(-v3));
            }
            *(float2*)(C + (size_t)m0 * N + n0)       = make_float2(v0, v1);
            *(float2*)(C + (size_t)(m0 + 8) * N + n0) = make_float2(v2, v3);
        }
    }
}

// ---------------------------------------------------------------------------
// Preprocessing: fp32 -> fp16 convert, and transpose+convert [K,N] -> [N,K]
// ---------------------------------------------------------------------------
__global__ void cvt_half(const float4* __restrict__ in, __half2* __restrict__ out,
                         int n4)
{
    int i = blockIdx.x * blockDim.x + threadIdx.x;
    if (i < n4) {
        float4 v = in[i];
        out[2 * i]     = __floats2half2_rn(v.x, v.y);
        out[2 * i + 1] = __floats2half2_rn(v.z, v.w);
    }
}
__global__ void transpose_half(const float* __restrict__ in, __half* __restrict__ out,
                               int K, int N)   // in[K][N] fp32 -> out[N][K] fp16
{
    __shared__ float t[32][33];
    const int n0 = blockIdx.x * 32, k0 = blockIdx.y * 32;
    const int x = threadIdx.x, y = threadIdx.y;
#pragma unroll
    for (int j = 0; j < 32; j += 8)
        t[y + j][x] = in[(size_t)(k0 + y + j) * N + n0 + x];
    __syncthreads();
#pragma unroll
    for (int j = 0; j < 32; j += 8)
        out[(size_t)(n0 + y + j) * K + k0 + x] = __float2half_rn(t[x][y + j]);
}

// ---------------------------------------------------------------------------
// Cumsum (2-phase): poly = c0 + c0*c1; per-chunk partials, then scan + causal
// mean + gate: sh = half(s * acc/(t+1))  (fp16 input for GEMM3)
// ---------------------------------------------------------------------------
__global__ void poly_partial(const float* __restrict__ h, float* __restrict__ part)
{
    const int ch = blockIdx.x * blockDim.x + threadIdx.x;
    const int c  = blockIdx.y, b = blockIdx.z;
    const float* hp = h + (size_t)b * TDIM * (2 * HDIM)
                        + (size_t)c * CLEN * (2 * HDIM) + ch;
    float acc = 0.f;
#pragma unroll 4
    for (int t = 0; t < CLEN; ++t) {
        float c0 = hp[(size_t)t * (2 * HDIM)];
        float c1 = hp[(size_t)t * (2 * HDIM) + HDIM];
        acc += fmaf(c0, c1, c0);
    }
    part[((size_t)b * NCH + c) * HDIM + ch] = acc;
}
__global__ void poly_scan_gate(const float* __restrict__ h,
                               const float* __restrict__ part,
                               const float* __restrict__ s,
                               __half* __restrict__ sh)
{
    const int ch = blockIdx.x * blockDim.x + threadIdx.x;
    const int c  = blockIdx.y, b = blockIdx.z;
    float acc = 0.f;
    for (int c2 = 0; c2 < c; ++c2)
        acc += part[((size_t)b * NCH + c2) * HDIM + ch];
    const float* hp = h + (size_t)b * TDIM * (2 * HDIM)
                        + (size_t)c * CLEN * (2 * HDIM) + ch;
    const float* sp = s + (size_t)b * TDIM * HDIM + (size_t)c * CLEN * HDIM + ch;
    __half* op = sh + (size_t)b * TDIM * HDIM + (size_t)c * CLEN * HDIM + ch;
    const int t0 = c * CLEN;
#pragma unroll 4
    for (int t = 0; t < CLEN; ++t) {
        float c0 = hp[(size_t)t * (2 * HDIM)];
        float c1 = hp[(size_t)t * (2 * HDIM) + HDIM];
        acc += fmaf(c0, c1, c0);
        float val = acc / (float)(t0 + t + 1);
        size_t off = (size_t)t * HDIM;
        op[off] = __float2half_rn(sp[off] * val);
    }
}

// ---------------------------------------------------------------------------
// Launch
// ---------------------------------------------------------------------------
extern "C" void kernel_launch(void* const* d_in, const int* in_sizes, int n_in,
                              void* d_out, int out_size)
{
    const float* x     = (const float*)d_in[0];
    const float* W_sel = (const float*)d_in[1];
    const float* W_agg = (const float*)d_in[2];
    const float* W_out = (const float*)d_in[3];
    const float* sqk_q = (const float*)d_in[4];
    const float* sqk_k = (const float*)d_in[5];
    float* out = (float*)d_out;

    float *s_p, *h_p, *part;
    __half *sh, *xh, *wsh, *wah, *woh;
    cudaGetSymbolAddress((void**)&s_p, g_s);
    cudaGetSymbolAddress((void**)&h_p, g_h);
    cudaGetSymbolAddress((void**)&sh, g_sh);
    cudaGetSymbolAddress((void**)&xh, g_xh);
    cudaGetSymbolAddress((void**)&wsh, g_wsh);
    cudaGetSymbolAddress((void**)&wah, g_wah);
    cudaGetSymbolAddress((void**)&woh, g_woh);
    cudaGetSymbolAddress((void**)&part, g_part);

    cudaFuncSetAttribute(hgemm<0>, cudaFuncAttributeMaxDynamicSharedMemorySize, SMEM_BYTES);
    cudaFuncSetAttribute(hgemm<1>, cudaFuncAttributeMaxDynamicSharedMemorySize, SMEM_BYTES);
    cudaFuncSetAttribute(hgemm<2>, cudaFuncAttributeMaxDynamicSharedMemorySize, SMEM_BYTES);

    // Preprocess: x -> fp16 ; weights -> transposed fp16 [N,K]
    {
        int n4 = MTOT * CDIM / 4;
        cvt_half<<<(n4 + 255) / 256, 256>>>((const float4*)x, (__half2*)xh, n4);
        dim3 tb(32, 8);
        transpose_half<<<dim3(HDIM / 32, CDIM / 32), tb>>>(W_sel, wsh, CDIM, HDIM);
        transpose_half<<<dim3(2 * HDIM / 32, CDIM / 32), tb>>>(W_agg, wah, CDIM, 2 * HDIM);
        transpose_half<<<dim3(CDIM / 32, HDIM / 32), tb>>>(W_out, woh, HDIM, CDIM);
    }

    dim3 blk(256);
    // s = silu((x @ W_sel) * sqk_q)            [16384 x 2048, K=1024] -> fp32
    hgemm<1><<<dim3(HDIM / BN, MTOT / BM), blk, SMEM_BYTES>>>(
        xh, wsh, s_p, sqk_q, MTOT, HDIM, CDIM);
    // h = (x @ W_agg) * sqk_k                  [16384 x 4096, K=1024] -> fp32
    hgemm<0><<<dim3(2 * HDIM / BN, MTOT / BM), blk, SMEM_BYTES>>>(
        xh, wah, h_p, sqk_k, MTOT, 2 * HDIM, CDIM);
    // poly -> causal running mean -> gate      (fp32 math, fp16 out)
    poly_partial<<<dim3(HDIM / 256, NCH, BDIM), 256>>>(h_p, part);
    poly_scan_gate<<<dim3(HDIM / 256, NCH, BDIM), 256>>>(h_p, part, s_p, sh);
    // out = (s*agg) @ W_out                    [16384 x 1024, K=2048] -> fp32
    hgemm<2><<<dim3(CDIM / BN, MTOT / BM), blk, SMEM_BYTES>>>(
        sh, woh, out, nullptr, MTOT, CDIM, HDIM);
}

// round 11
// speedup vs baseline: 9.6968x; 1.0461x over previous
#include <cuda_runtime.h>
#include <cuda_fp16.h>
#include <cstdint>
#include <math.h>

// Problem constants
#define BDIM 4
#define TDIM 4096
#define CDIM 1024
#define HDIM 2048
#define MTOT (BDIM * TDIM)   // 16384
#define NCH  32              // cumsum chunks
#define CLEN (TDIM / NCH)    // 128

// Scratch (device globals: allocation-free per harness rules)
__device__ float  g_s [(size_t)MTOT * HDIM];        // silu branch (fp32)
__device__ __half g_hh[(size_t)MTOT * 2 * HDIM];    // agg branch (fp16)
__device__ __half g_sh[(size_t)MTOT * HDIM];        // gated s*agg (fp16, GEMM3 A)
__device__ __half g_xh[(size_t)MTOT * CDIM];        // x fp16
__device__ __half g_wsh[(size_t)HDIM * CDIM];       // W_sel^T fp16 [N,K]
__device__ __half g_wah[(size_t)2 * HDIM * CDIM];   // W_agg^T fp16 [N,K]
__device__ __half g_woh[(size_t)CDIM * HDIM];       // W_out^T fp16 [N,K]
__device__ float  g_part[BDIM * NCH * HDIM];        // cumsum partials

// ---------------------------------------------------------------------------
// PTX helpers (plain sm_80-era features only: compile under compute_103)
// ---------------------------------------------------------------------------
__device__ __forceinline__ void cpasync16(uint32_t saddr, const void* g) {
    asm volatile("cp.async.cg.shared.global [%0], [%1], 16;" :: "r"(saddr), "l"(g));
}
__device__ __forceinline__ void ldsm4(uint32_t* r, uint32_t saddr) {
    asm volatile("ldmatrix.sync.aligned.m8n8.x4.shared.b16 {%0,%1,%2,%3}, [%4];"
                 : "=r"(r[0]), "=r"(r[1]), "=r"(r[2]), "=r"(r[3]) : "r"(saddr));
}
__device__ __forceinline__ void mma_f16(float* c, const uint32_t* a,
                                        uint32_t b0, uint32_t b1) {
    asm volatile(
        "mma.sync.aligned.m16n8k16.row.col.f32.f16.f16.f32 "
        "{%0,%1,%2,%3}, {%4,%5,%6,%7}, {%8,%9}, {%0,%1,%2,%3};"
        : "+f"(c[0]), "+f"(c[1]), "+f"(c[2]), "+f"(c[3])
        : "r"(a[0]), "r"(a[1]), "r"(a[2]), "r"(a[3]), "r"(b0), "r"(b1));
}

// ---------------------------------------------------------------------------
// fp16 tensor-core GEMM: C[M,N] = A[M,K](fp16) @ Wt[N,K](fp16)^T.
// 128x128 block tile, BK=64 halves, 3-stage cp.async ring, 8 warps (2x4),
// warp tile 64x32. A AND B fragments via ldmatrix (144B padded rows:
// stride 36 words == 4 mod 32 -> all ldmatrix phases conflict-free).
// EPI: 0 = y*scale[n] ; 1 = silu(y*scale[n]) ; 2 = plain.  TO: float | __half
// ---------------------------------------------------------------------------
constexpr int BM = 128, BN = 128, BKH = 64;
constexpr int KPAD = 72;                       // halves per padded row
constexpr int ROWB = KPAD * 2;                 // 144 bytes per row
constexpr int ATILE_B = BM * ROWB;             // 18432 bytes
constexpr int STAGE_B = 2 * ATILE_B;           // A + B per stage (36864)
constexpr int STAGES = 3;
constexpr int SMEM_BYTES = STAGES * STAGE_B;   // 110592

template <int EPI, typename TO>
__global__ __launch_bounds__(256, 2)
void hgemm(const __half* __restrict__ A, const __half* __restrict__ Wt,
           TO* __restrict__ C, const float* __restrict__ scale,
           int M, int N, int K)
{
    extern __shared__ __half sm[];
    const uint32_t smb = (uint32_t)__cvta_generic_to_shared(sm);

    const int tid  = threadIdx.x;
    const int lane = tid & 31;
    const int wid  = tid >> 5;
    const int wm   = (wid >> 2) * 64;     // warp m offset
    const int wn   = (wid & 3) * 32;      // warp n offset
    const int bm   = blockIdx.y * BM;
    const int bn   = blockIdx.x * BN;
    const int nt   = K / BKH;

    // A ldmatrix.x4 lane offset: row = lane%16, kcol = (lane/16)*8 halves
    const uint32_t a_lane = (uint32_t)((lane & 15) * ROWB + (lane >> 4) * 16);
    // B ldmatrix.x4 lane offset: g=lane/8 -> matrices [j kh0, j kh1, j+1 kh0, j+1 kh1]
    {
    }
    const int bg = lane >> 3, br = lane & 7;
    const uint32_t b_lane = (uint32_t)(((bg >> 1) * 8 + br) * ROWB + (bg & 1) * 16);

    auto issue_tile = [&](int t, int s) {
        const int k0 = t * BKH;
        const uint32_t ab = smb + (uint32_t)s * STAGE_B;
        const uint32_t bb = ab + ATILE_B;
#pragma unroll
        for (int i = 0; i < 4; ++i) {
            int idx = tid + (i << 8);            // 0..1023
            int r = idx >> 3, c = idx & 7;
            uint32_t dst = (uint32_t)(r * ROWB + c * 16);
            cpasync16(ab + dst, A  + (size_t)(bm + r) * K + k0 + c * 8);
            cpasync16(bb + dst, Wt + (size_t)(bn + r) * K + k0 + c * 8);
        }
    };

    // Prologue: fill ring
    issue_tile(0, 0);
    asm volatile("cp.async.commit_group;");
    issue_tile(1, 1);
    asm volatile("cp.async.commit_group;");
    issue_tile(2, 2);
    asm volatile("cp.async.commit_group;");
    asm volatile("cp.async.wait_group 2;");
    __syncthreads();

    float acc[4][4][4];
#pragma unroll
    for (int i = 0; i < 4; ++i)
#pragma unroll
        for (int j = 0; j < 4; ++j)
#pragma unroll
            for (int q = 0; q < 4; ++q) acc[i][j][q] = 0.f;

    int buf = 0;
    for (int t = 0; t < nt; ++t) {
        const uint32_t ab = smb + (uint32_t)buf * STAGE_B;
        const uint32_t bb = ab + ATILE_B;
#pragma unroll
        for (int ks = 0; ks < 4; ++ks) {         // 4 x k16
            uint32_t af[4][4];
#pragma unroll
            for (int i = 0; i < 4; ++i)
                ldsm4(af[i], ab + (uint32_t)((wm + i * 16) * ROWB + ks * 32) + a_lane);
            uint32_t bf[2][4];                   // [jj][m0..m3]
#pragma unroll
            for (int jj = 0; jj < 2; ++jj)
                ldsm4(bf[jj], bb + (uint32_t)((wn + jj * 16) * ROWB + ks * 32) + b_lane);
#pragma unroll
            for (int i = 0; i < 4; ++i) {
#pragma unroll
                for (int jj = 0; jj < 2; ++jj) {
                    mma_f16(acc[i][2 * jj],     af[i], bf[jj][0], bf[jj][1]);
                    mma_f16(acc[i][2 * jj + 1], af[i], bf[jj][2], bf[jj][3]);
                }
            }
        }
        __syncthreads();                         // done reading buf
        if (t + STAGES < nt) issue_tile(t + STAGES, buf);
        asm volatile("cp.async.commit_group;");
        asm volatile("cp.async.wait_group 2;");  // tile t+1 landed
        __syncthreads();
        buf = (buf == STAGES - 1) ? 0 : buf + 1;
    }

    // Epilogue: direct fragment stores
    const int qr = lane >> 2;              // 0..7
    const int qc = (lane & 3) << 1;        // 0,2,4,6
#pragma unroll
    for (int i = 0; i < 4; ++i) {
        const int m0 = bm + wm + i * 16 + qr;
#pragma unroll
        for (int j = 0; j < 4; ++j) {
            const int n0 = bn + wn + j * 8 + qc;
            float v0 = acc[i][j][0], v1 = acc[i][j][1];
            float v2 = acc[i][j][2], v3 = acc[i][j][3];
            if (EPI == 0 || EPI == 1) {
                float s0 = scale[n0], s1 = scale[n0 + 1];
                v0 *= s0; v1 *= s1; v2 *= s0; v3 *= s1;
            }
            if (EPI == 1) {
                v0 = v0 / (1.f + __expf(-v0));
                v1 = v1 / (1.f + __expf(-v1));
                v2 = v2 / (1.f + __expf(-v2));
                v3 = v3 / (1.f + __expf(-v3));
            }
            if (sizeof(TO) == 2) {   // fp16 output: packed 4B stores
                __half2 p0 = __floats2half2_rn(v0, v1);
                __half2 p1 = __floats2half2_rn(v2, v3);
                *(__half2*)((__half*)C + (size_t)m0 * N + n0)       = p0;
                *(__half2*)((__half*)C + (size_t)(m0 + 8) * N + n0) = p1;
            } else {
                *(float2*)((float*)C + (size_t)m0 * N + n0)       = make_float2(v0, v1);
                *(float2*)((float*)C + (size_t)(m0 + 8) * N + n0) = make_float2(v2, v3);
            }
        }
    }
}

// ---------------------------------------------------------------------------
// Preprocessing: fp32 -> fp16 convert, and transpose+convert [K,N] -> [N,K]
// ---------------------------------------------------------------------------
__global__ void cvt_half(const float4* __restrict__ in, __half2* __restrict__ out,
                         int n4)
{
    int i = blockIdx.x * blockDim.x + threadIdx.x;
    if (i < n4) {
        float4 v = in[i];
        out[2 * i]     = __floats2half2_rn(v.x, v.y);
        out[2 * i + 1] = __floats2half2_rn(v.z, v.w);
    }
}
__global__ void transpose_half(const float* __restrict__ in, __half* __restrict__ out,
                               int K, int N)   // in[K][N] fp32 -> out[N][K] fp16
{
    __shared__ float t[32][33];
    const int n0 = blockIdx.x * 32, k0 = blockIdx.y * 32;
    const int x = threadIdx.x, y = threadIdx.y;
#pragma unroll
    for (int j = 0; j < 32; j += 8)
        t[y + j][x] = in[(size_t)(k0 + y + j) * N + n0 + x];
    __syncthreads();
#pragma unroll
    for (int j = 0; j < 32; j += 8)
        out[(size_t)(n0 + y + j) * K + k0 + x] = __float2half_rn(t[x][y + j]);
}

// ---------------------------------------------------------------------------
// Cumsum (2-phase, half2-vectorized): poly = c0 + c0*c1.
// Phase 1: per-chunk partial sums. Phase 2: scan + causal mean + gate
//   sh = half(s * acc/(t+1))   (fp16 input for GEMM3)
// h rows: 2*HDIM halves = HDIM half2; c1 at +HDIM/2 half2.
// ---------------------------------------------------------------------------
__global__ void poly_partial(const __half2* __restrict__ h2,
                             float2* __restrict__ part2)
{
    const int ch2 = blockIdx.x * blockDim.x + threadIdx.x;   // 0..HDIM/2-1
    const int c  = blockIdx.y, b = blockIdx.z;
    const __half2* hp = h2 + ((size_t)b * TDIM + (size_t)c * CLEN) * HDIM + ch2;
    float2 acc = make_float2(0.f, 0.f);
#pragma unroll 4
    for (int t = 0; t < CLEN; ++t) {
        float2 c0 = __half22float2(hp[(size_t)t * HDIM]);
        float2 c1 = __half22float2(hp[(size_t)t * HDIM + HDIM / 2]);
        acc.x += fmaf(c0.x, c1.x, c0.x);
        acc.y += fmaf(c0.y, c1.y, c0.y);
    }
    part2[((size_t)b * NCH + c) * (HDIM / 2) + ch2] = acc;
}
__global__ void poly_scan_gate(const __half2* __restrict__ h2,
                               const float2* __restrict__ part2,
                               const float2* __restrict__ s2,
                               __half2* __restrict__ sh2)
{
    const int ch2 = blockIdx.x * blockDim.x + threadIdx.x;
    const int c  = blockIdx.y, b = blockIdx.z;
    float2 acc = make_float2(0.f, 0.f);
    for (int c2 = 0; c2 < c; ++c2) {
        float2 p = part2[((size_t)b * NCH + c2) * (HDIM / 2) + ch2];
        acc.x += p.x; acc.y += p.y;
    }
    const __half2* hp = h2 + ((size_t)b * TDIM + (size_t)c * CLEN) * HDIM + ch2;
    const float2* sp = s2 + ((size_t)b * TDIM + (size_t)c * CLEN) * (HDIM / 2) + ch2;
    __half2* op = sh2 + ((size_t)b * TDIM + (size_t)c * CLEN) * (HDIM / 2) + ch2;
    const int t0 = c * CLEN;
#pragma unroll 4
    for (int t = 0; t < CLEN; ++t) {
        float2 c0 = __half22float2(hp[(size_t)t * HDIM]);
        float2 c1 = __half22float2(hp[(size_t)t * HDIM + HDIM / 2]);
        acc.x += fmaf(c0.x, c1.x, c0.x);
        acc.y += fmaf(c0.y, c1.y, c0.y);
        float inv = 1.0f / (float)(t0 + t + 1);
        float2 sv = sp[(size_t)t * (HDIM / 2)];
        op[(size_t)t * (HDIM / 2)] =
            __floats2half2_rn(sv.x * acc.x * inv, sv.y * acc.y * inv);
    }
}

// ---------------------------------------------------------------------------
// Launch
// ---------------------------------------------------------------------------
extern "C" void kernel_launch(void* const* d_in, const int* in_sizes, int n_in,
                              void* d_out, int out_size)
{
    const float* x     = (const float*)d_in[0];
    const float* W_sel = (const float*)d_in[1];
    const float* W_agg = (const float*)d_in[2];
    const float* W_out = (const float*)d_in[3];
    const float* sqk_q = (const float*)d_in[4];
    const float* sqk_k = (const float*)d_in[5];
    float* out = (float*)d_out;

    float *s_p, *part;
    __half *hh, *sh, *xh, *wsh, *wah, *woh;
    cudaGetSymbolAddress((void**)&s_p, g_s);
    cudaGetSymbolAddress((void**)&hh, g_hh);
    cudaGetSymbolAddress((void**)&sh, g_sh);
    cudaGetSymbolAddress((void**)&xh, g_xh);
    cudaGetSymbolAddress((void**)&wsh, g_wsh);
    cudaGetSymbolAddress((void**)&wah, g_wah);
    cudaGetSymbolAddress((void**)&woh, g_woh);
    cudaGetSymbolAddress((void**)&part, g_part);

    cudaFuncSetAttribute((const void*)hgemm<0, __half>,
                         cudaFuncAttributeMaxDynamicSharedMemorySize, SMEM_BYTES);
    cudaFuncSetAttribute((const void*)hgemm<1, float>,
                         cudaFuncAttributeMaxDynamicSharedMemorySize, SMEM_BYTES);
    cudaFuncSetAttribute((const void*)hgemm<2, float>,
                         cudaFuncAttributeMaxDynamicSharedMemorySize, SMEM_BYTES);

    // Preprocess: x -> fp16 ; weights -> transposed fp16 [N,K]
    {
        int n4 = MTOT * CDIM / 4;
        cvt_half<<<(n4 + 255) / 256, 256>>>((const float4*)x, (__half2*)xh, n4);
        dim3 tb(32, 8);
        transpose_half<<<dim3(HDIM / 32, CDIM / 32), tb>>>(W_sel, wsh, CDIM, HDIM);
        transpose_half<<<dim3(2 * HDIM / 32, CDIM / 32), tb>>>(W_agg, wah, CDIM, 2 * HDIM);
        transpose_half<<<dim3(CDIM / 32, HDIM / 32), tb>>>(W_out, woh, HDIM, CDIM);
    }

    dim3 blk(256);
    // s = silu((x @ W_sel) * sqk_q)            [16384 x 2048, K=1024] -> fp32
    hgemm<1, float><<<dim3(HDIM / BN, MTOT / BM), blk, SMEM_BYTES>>>(
        xh, wsh, s_p, sqk_q, MTOT, HDIM, CDIM);
    // h = (x @ W_agg) * sqk_k                  [16384 x 4096, K=1024] -> fp16
    hgemm<0, __half><<<dim3(2 * HDIM / BN, MTOT / BM), blk, SMEM_BYTES>>>(
        xh, wah, hh, sqk_k, MTOT, 2 * HDIM, CDIM);
    // poly -> causal running mean -> gate      (fp32 math, fp16 out)
    poly_partial<<<dim3(HDIM / 2 / 256, NCH, BDIM), 256>>>(
        (const __half2*)hh, (float2*)part);
    poly_scan_gate<<<dim3(HDIM / 2 / 256, NCH, BDIM), 256>>>(
        (const __half2*)hh, (const float2*)part, (const float2*)s_p, (__half2*)sh);
    // out = (s*agg) @ W_out                    [16384 x 1024, K=2048] -> fp32
    hgemm<2, float><<<dim3(CDIM / BN, MTOT / BM), blk, SMEM_BYTES>>>(
        sh, woh, out, nullptr, MTOT, CDIM, HDIM);
}

// round 12
// speedup vs baseline: 9.8621x; 1.0171x over previous
#include <cuda_runtime.h>
#include <cuda_fp16.h>
#include <cstdint>
#include <math.h>

// Problem constants
#define BDIM 4
#define TDIM 4096
#define CDIM 1024
#define HDIM 2048
#define MTOT (BDIM * TDIM)   // 16384
#define NCH  32              // cumsum chunks
#define CLEN (TDIM / NCH)    // 128

// Scratch (device globals: allocation-free per harness rules)
__device__ float  g_s [(size_t)MTOT * HDIM];        // silu branch (fp32)
__device__ __half g_hh[(size_t)MTOT * 2 * HDIM];    // agg branch (fp16)
__device__ __half g_sh[(size_t)MTOT * HDIM];        // gated s*agg (fp16, GEMM3 A)
__device__ __half g_xh[(size_t)MTOT * CDIM];        // x fp16
__device__ __half g_wsh[(size_t)HDIM * CDIM];       // W_sel^T fp16 [N,K]
__device__ __half g_wah[(size_t)2 * HDIM * CDIM];   // W_agg^T fp16 [N,K]
__device__ __half g_woh[(size_t)CDIM * HDIM];       // W_out^T fp16 [N,K]
__device__ float  g_part[BDIM * NCH * HDIM];        // cumsum partials

// ---------------------------------------------------------------------------
// PTX helpers (plain sm_80-era features only: compile under compute_103)
// ---------------------------------------------------------------------------
__device__ __forceinline__ void cpasync16(uint32_t saddr, const void* g) {
    asm volatile("cp.async.cg.shared.global [%0], [%1], 16;" :: "r"(saddr), "l"(g));
}
__device__ __forceinline__ void ldsm4(uint32_t* r, uint32_t saddr) {
    asm volatile("ldmatrix.sync.aligned.m8n8.x4.shared.b16 {%0,%1,%2,%3}, [%4];"
                 : "=r"(r[0]), "=r"(r[1]), "=r"(r[2]), "=r"(r[3]) : "r"(saddr));
}
__device__ __forceinline__ void mma_f16(float* c, const uint32_t* a,
                                        uint32_t b0, uint32_t b1) {
    asm volatile(
        "mma.sync.aligned.m16n8k16.row.col.f32.f16.f16.f32 "
        "{%0,%1,%2,%3}, {%4,%5,%6,%7}, {%8,%9}, {%0,%1,%2,%3};"
        : "+f"(c[0]), "+f"(c[1]), "+f"(c[2]), "+f"(c[3])
        : "r"(a[0]), "r"(a[1]), "r"(a[2]), "r"(a[3]), "r"(b0), "r"(b1));
}

// ---------------------------------------------------------------------------
// fp16 tensor-core GEMM: C[M,N] = A[M,K](fp16) @ Wt[N,K](fp16)^T.
// 128x128 block tile, BK=64 halves, 3-stage cp.async ring, 8 warps (2x4),
// warp tile 64x32, A+B fragments via ldmatrix (144B padded rows).
// CUTLASS-style multistage schedule: issue loads for tile t+2 FIRST, then
// compute tile t, then wait+single-sync. One barrier per k-tile.
// EPI: 0 = y*scale[n] ; 1 = silu(y*scale[n]) ; 2 = plain.  TO: float | __half
// ---------------------------------------------------------------------------
constexpr int BM = 128, BN = 128, BKH = 64;
constexpr int KPAD = 72;                       // halves per padded row
constexpr int ROWB = KPAD * 2;                 // 144 bytes per row
constexpr int ATILE_B = BM * ROWB;             // 18432 bytes
constexpr int STAGE_B = 2 * ATILE_B;           // A + B per stage (36864)
constexpr int STAGES = 3;
constexpr int SMEM_BYTES = STAGES * STAGE_B;   // 110592

template <int EPI, typename TO>
__global__ __launch_bounds__(256, 2)
void hgemm(const __half* __restrict__ A, const __half* __restrict__ Wt,
           TO* __restrict__ C, const float* __restrict__ scale,
           int M, int N, int K)
{
    extern __shared__ __half sm[];
    const uint32_t smb = (uint32_t)__cvta_generic_to_shared(sm);

    const int tid  = threadIdx.x;
    const int lane = tid & 31;
    const int wid  = tid >> 5;
    const int wm   = (wid >> 2) * 64;     // warp m offset
    const int wn   = (wid & 3) * 32;      // warp n offset
    const int bm   = blockIdx.y * BM;
    const int bn   = blockIdx.x * BN;
    const int nt   = K / BKH;

    // A ldmatrix.x4 lane offset: row = lane%16, kcol = (lane/16)*8 halves
    const uint32_t a_lane = (uint32_t)((lane & 15) * ROWB + (lane >> 4) * 16);
    // B ldmatrix.x4 lane offset
    const int bg = lane >> 3, br = lane & 7;
    const uint32_t b_lane = (uint32_t)(((bg >> 1) * 8 + br) * ROWB + (bg & 1) * 16);

    auto issue_tile = [&](int t, int s) {
        const int k0 = t * BKH;
        const uint32_t ab = smb + (uint32_t)s * STAGE_B;
        const uint32_t bb = ab + ATILE_B;
#pragma unroll
        for (int i = 0; i < 4; ++i) {
            int idx = tid + (i << 8);            // 0..1023
            int r = idx >> 3, c = idx & 7;
            uint32_t dst = (uint32_t)(r * ROWB + c * 16);
            cpasync16(ab + dst, A  + (size_t)(bm + r) * K + k0 + c * 8);
            cpasync16(bb + dst, Wt + (size_t)(bn + r) * K + k0 + c * 8);
        }
    };

    // Prologue: tiles 0 and 1 in flight; wait for tile 0.
    issue_tile(0, 0);
    asm volatile("cp.async.commit_group;");
    issue_tile(1, 1);
    asm volatile("cp.async.commit_group;");
    asm volatile("cp.async.wait_group 1;");
    __syncthreads();

    float acc[4][4][4];
#pragma unroll
    for (int i = 0; i < 4; ++i)
#pragma unroll
        for (int j = 0; j < 4; ++j)
#pragma unroll
            for (int q = 0; q < 4; ++q) acc[i][j][q] = 0.f;

    for (int t = 0; t < nt; ++t) {
        const int buf = t % STAGES;
        // 1) Issue tile t+2 into the buffer consumed at iter t-1 (safe: the
        //    single barrier at the end of iter t-1 ordered all reads of it).
        if (t + 2 < nt) issue_tile(t + 2, (t + 2) % STAGES);
        asm volatile("cp.async.commit_group;");

        // 2) Compute tile t (landed & visible).
        const uint32_t ab = smb + (uint32_t)buf * STAGE_B;
        const uint32_t bb = ab + ATILE_B;
#pragma unroll
        for (int ks = 0; ks < 4; ++ks) {         // 4 x k16
            uint32_t af[4][4];
#pragma unroll
            for (int i = 0; i < 4; ++i)
                ldsm4(af[i], ab + (uint32_t)((wm + i * 16) * ROWB + ks * 32) + a_lane);
            uint32_t bf[2][4];
#pragma unroll
            for (int jj = 0; jj < 2; ++jj)
                ldsm4(bf[jj], bb + (uint32_t)((wn + jj * 16) * ROWB + ks * 32) + b_lane);
#pragma unroll
            for (int i = 0; i < 4; ++i) {
#pragma unroll
                for (int jj = 0; jj < 2; ++jj) {
                    mma_f16(acc[i][2 * jj],     af[i], bf[jj][0], bf[jj][1]);
                    mma_f16(acc[i][2 * jj + 1], af[i], bf[jj][2], bf[jj][3]);
                }
            }
        }

        // 3) Tile t+1 must have landed; one barrier closes the iteration.
        asm volatile("cp.async.wait_group 1;");
        __syncthreads();
    }

    // Epilogue: direct fragment stores
    const int qr = lane >> 2;              // 0..7
    const int qc = (lane & 3) << 1;        // 0,2,4,6
#pragma unroll
    for (int i = 0; i < 4; ++i) {
        const int m0 = bm + wm + i * 16 + qr;
#pragma unroll
        for (int j = 0; j < 4; ++j) {
            const int n0 = bn + wn + j * 8 + qc;
            float v0 = acc[i][j][0], v1 = acc[i][j][1];
            float v2 = acc[i][j][2], v3 = acc[i][j][3];
            if (EPI == 0 || EPI == 1) {
                float s0 = scale[n0], s1 = scale[n0 + 1];
                v0 *= s0; v1 *= s1; v2 *= s0; v3 *= s1;
            }
            if (EPI == 1) {
                v0 = v0 / (1.f + __expf(-v0));
                v1 = v1 / (1.f + __expf(-v1));
                v2 = v2 / (1.f + __expf(-v2));
                v3 = v3 / (1.f + __expf(-v3));
            }
            if (sizeof(TO) == 2) {   // fp16 output: packed 4B stores
                __half2 p0 = __floats2half2_rn(v0, v1);
                __half2 p1 = __floats2half2_rn(v2, v3);
                *(__half2*)((__half*)C + (size_t)m0 * N + n0)       = p0;
                *(__half2*)((__half*)C + (size_t)(m0 + 8) * N + n0) = p1;
            } else {
                *(float2*)((float*)C + (size_t)m0 * N + n0)       = make_float2(v0, v1);
                *(float2*)((float*)C + (size_t)(m0 + 8) * N + n0) = make_float2(v2, v3);
            }
        }
    }
}

// ---------------------------------------------------------------------------
// Preprocessing: fp32 -> fp16 convert, and transpose+convert [K,N] -> [N,K]
// ---------------------------------------------------------------------------
__global__ void cvt_half(const float4* __restrict__ in, __half2* __restrict__ out,
                         int n4)
{
    int i = blockIdx.x * blockDim.x + threadIdx.x;
    if (i < n4) {
        float4 v = in[i];
        out[2 * i]     = __floats2half2_rn(v.x, v.y);
        out[2 * i + 1] = __floats2half2_rn(v.z, v.w);
    }
}
__global__ void transpose_half(const float* __restrict__ in, __half* __restrict__ out,
                               int K, int N)   // in[K][N] fp32 -> out[N][K] fp16
{
    __shared__ float t[32][33];
    const int n0 = blockIdx.x * 32, k0 = blockIdx.y * 32;
    const int x = threadIdx.x, y = threadIdx.y;
#pragma unroll
    for (int j = 0; j < 32; j += 8)
        t[y + j][x] = in[(size_t)(k0 + y + j) * N + n0 + x];
    __syncthreads();
#pragma unroll
    for (int j = 0; j < 32; j += 8)
        out[(size_t)(n0 + y + j) * K + k0 + x] = __float2half_rn(t[x][y + j]);
}

// ---------------------------------------------------------------------------
// Cumsum (2-phase, half2-vectorized): poly = c0 + c0*c1.
// Phase 1: per-chunk partial sums. Phase 2: scan + causal mean + gate
//   sh = half(s * acc/(t+1))   (fp16 input for GEMM3)
// ---------------------------------------------------------------------------
__global__ void poly_partial(const __half2* __restrict__ h2,
                             float2* __restrict__ part2)
{
    const int ch2 = blockIdx.x * blockDim.x + threadIdx.x;   // 0..HDIM/2-1
    const int c  = blockIdx.y, b = blockIdx.z;
    const __half2* hp = h2 + ((size_t)b * TDIM + (size_t)c * CLEN) * HDIM + ch2;
    float2 acc = make_float2(0.f, 0.f);
#pragma unroll 4
    for (int t = 0; t < CLEN; ++t) {
        float2 c0 = __half22float2(hp[(size_t)t * HDIM]);
        float2 c1 = __half22float2(hp[(size_t)t * HDIM + HDIM / 2]);
        acc.x += fmaf(c0.x, c1.x, c0.x);
        acc.y += fmaf(c0.y, c1.y, c0.y);
    }
    part2[((size_t)b * NCH + c) * (HDIM / 2) + ch2] = acc;
}
__global__ void poly_scan_gate(const __half2* __restrict__ h2,
                               const float2* __restrict__ part2,
                               const float2* __restrict__ s2,
                               __half2* __restrict__ sh2)
{
    const int ch2 = blockIdx.x * blockDim.x + threadIdx.x;
    const int c  = blockIdx.y, b = blockIdx.z;
    float2 acc = make_float2(0.f, 0.f);
    for (int c2 = 0; c2 < c; ++c2) {
        float2 p = part2[((size_t)b * NCH + c2) * (HDIM / 2) + ch2];
        acc.x += p.x; acc.y += p.y;
    }
    const __half2* hp = h2 + ((size_t)b * TDIM + (size_t)c * CLEN) * HDIM + ch2;
    const float2* sp = s2 + ((size_t)b * TDIM + (size_t)c * CLEN) * (HDIM / 2) + ch2;
    __half2* op = sh2 + ((size_t)b * TDIM + (size_t)c * CLEN) * (HDIM / 2) + ch2;
    const int t0 = c * CLEN;
#pragma unroll 4
    for (int t = 0; t < CLEN; ++t) {
        float2 c0 = __half22float2(hp[(size_t)t * HDIM]);
        float2 c1 = __half22float2(hp[(size_t)t * HDIM + HDIM / 2]);
        acc.x += fmaf(c0.x, c1.x, c0.x);
        acc.y += fmaf(c0.y, c1.y, c0.y);
        float inv = 1.0f / (float)(t0 + t + 1);
        float2 sv = sp[(size_t)t * (HDIM / 2)];
        op[(size_t)t * (HDIM / 2)] =
            __floats2half2_rn(sv.x * acc.x * inv, sv.y * acc.y * inv);
    }
}

// ---------------------------------------------------------------------------
// Launch
// ---------------------------------------------------------------------------
extern "C" void kernel_launch(void* const* d_in, const int* in_sizes, int n_in,
                              void* d_out, int out_size)
{
    const float* x     = (const float*)d_in[0];
    const float* W_sel = (const float*)d_in[1];
    const float* W_agg = (const float*)d_in[2];
    const float* W_out = (const float*)d_in[3];
    const float* sqk_q = (const float*)d_in[4];
    const float* sqk_k = (const float*)d_in[5];
    float* out = (float*)d_out;

    float *s_p, *part;
    __half *hh, *sh, *xh, *wsh, *wah, *woh;
    cudaGetSymbolAddress((void**)&s_p, g_s);
    cudaGetSymbolAddress((void**)&hh, g_hh);
    cudaGetSymbolAddress((void**)&sh, g_sh);
    cudaGetSymbolAddress((void**)&xh, g_xh);
    cudaGetSymbolAddress((void**)&wsh, g_wsh);
    cudaGetSymbolAddress((void**)&wah, g_wah);
    cudaGetSymbolAddress((void**)&woh, g_woh);
    cudaGetSymbolAddress((void**)&part, g_part);

    cudaFuncSetAttribute((const void*)hgemm<0, __half>,
                         cudaFuncAttributeMaxDynamicSharedMemorySize, SMEM_BYTES);
    cudaFuncSetAttribute((const void*)hgemm<1, float>,
                         cudaFuncAttributeMaxDynamicSharedMemorySize, SMEM_BYTES);
    cudaFuncSetAttribute((const void*)hgemm<2, float>,
                         cudaFuncAttributeMaxDynamicSharedMemorySize, SMEM_BYTES);

    // Preprocess: x -> fp16 ; weights -> transposed fp16 [N,K]
    {
        int n4 = MTOT * CDIM / 4;
        cvt_half<<<(n4 + 255) / 256, 256>>>((const float4*)x, (__half2*)xh, n4);
        dim3 tb(32, 8);
        transpose_half<<<dim3(HDIM / 32, CDIM / 32), tb>>>(W_sel, wsh, CDIM, HDIM);
        transpose_half<<<dim3(2 * HDIM / 32, CDIM / 32), tb>>>(W_agg, wah, CDIM, 2 * HDIM);
        transpose_half<<<dim3(CDIM / 32, HDIM / 32), tb>>>(W_out, woh, HDIM, CDIM);
    }

    dim3 blk(256);
    // s = silu((x @ W_sel) * sqk_q)            [16384 x 2048, K=1024] -> fp32
    hgemm<1, float><<<dim3(HDIM / BN, MTOT / BM), blk, SMEM_BYTES>>>(
        xh, wsh, s_p, sqk_q, MTOT, HDIM, CDIM);
    // h = (x @ W_agg) * sqk_k                  [16384 x 4096, K=1024] -> fp16
    hgemm<0, __half><<<dim3(2 * HDIM / BN, MTOT / BM), blk, SMEM_BYTES>>>(
        xh, wah, hh, sqk_k, MTOT, 2 * HDIM, CDIM);
    // poly -> causal running mean -> gate      (fp32 math, fp16 out)
    poly_partial<<<dim3(HDIM / 2 / 256, NCH, BDIM), 256>>>(
        (const __half2*)hh, (float2*)part);
    poly_scan_gate<<<dim3(HDIM / 2 / 256, NCH, BDIM), 256>>>(
        (const __half2*)hh, (const float2*)part, (const float2*)s_p, (__half2*)sh);
    // out = (s*agg) @ W_out                    [16384 x 1024, K=2048] -> fp32
    hgemm<2, float><<<dim3(CDIM / BN, MTOT / BM), blk, SMEM_BYTES>>>(
        sh, woh, out, nullptr, MTOT, CDIM, HDIM);
}